// round 1
// baseline (speedup 1.0000x reference)
#include <cuda_runtime.h>
#include <cstdint>

#define T_STEPS 512
#define B_SZ 64
#define D_SZ 1024
#define H_SZ 1024
#define G4 4096
#define M_TOT (T_STEPS * B_SZ)   // 32768

// ---------------- device scratch (static, allocation-free) ----------------
__device__ float g_Wx[D_SZ * G4];                 // 16 MB, packed col j = n*4+g
__device__ float g_Wh[H_SZ * G4];                 // 16 MB, packed
__device__ float g_b4[G4];                        // packed bias
__device__ float g_Gx[(size_t)M_TOT * G4];        // 512 MB precomputed x-projection (+bias)
__device__ float g_h[2][B_SZ * H_SZ];             // double-buffered hidden state
__device__ float g_c[B_SZ * H_SZ];                // cell state

// ---------------- helpers ----------------
__device__ __forceinline__ uint32_t f2tf32(float f) {
    uint32_t r;
    asm volatile("cvt.rna.tf32.f32 %0, %1;" : "=r"(r) : "f"(f));
    return r;
}

__device__ __forceinline__ void mma_tf32(float* c, const uint32_t* a, const uint32_t* b) {
    asm volatile(
        "mma.sync.aligned.m16n8k8.row.col.f32.tf32.tf32.f32 "
        "{%0,%1,%2,%3}, {%4,%5,%6,%7}, {%8,%9}, {%0,%1,%2,%3};"
        : "+f"(c[0]), "+f"(c[1]), "+f"(c[2]), "+f"(c[3])
        : "r"(a[0]), "r"(a[1]), "r"(a[2]), "r"(a[3]), "r"(b[0]), "r"(b[1]));
}

__device__ __forceinline__ float sigmoidf_fast(float x) {
    return 1.0f / (1.0f + __expf(-x));
}

// ---------------- kernel 0: repack weights/bias, zero state ----------------
// Packed layout: column j = n*4 + g  (g: 0=f,1=i,2=g,3=o), so each h-column's
// 4 gates are adjacent -> per-step blocks own complete gate quadruples.
__global__ void pack_kernel(const float* __restrict__ Wf, const float* __restrict__ Wi,
                            const float* __restrict__ Wg, const float* __restrict__ Wo,
                            const float* __restrict__ bf, const float* __restrict__ bi,
                            const float* __restrict__ bg, const float* __restrict__ bo) {
    int idx = blockIdx.x * blockDim.x + threadIdx.x;   // over D_SZ*G4 = 4M
    if (idx < D_SZ * G4) {
        int k = idx >> 12;       // row
        int j = idx & 4095;      // packed col
        int n = j >> 2;
        int g = j & 3;
        const float* W = (g == 0) ? Wf : (g == 1) ? Wi : (g == 2) ? Wg : Wo;
        g_Wx[idx] = W[k * H_SZ + n];
        g_Wh[idx] = W[(D_SZ + k) * H_SZ + n];
    }
    if (idx < G4) {
        int n = idx >> 2, g = idx & 3;
        const float* bb = (g == 0) ? bf : (g == 1) ? bi : (g == 2) ? bg : bo;
        g_b4[idx] = bb[n];
    }
    if (idx < B_SZ * H_SZ) {
        g_h[0][idx] = 0.0f;
        g_c[idx] = 0.0f;
    }
}

// ---------------- kernel 1: Gx = X @ Wx + b  (tf32 MMA) ----------------
// M=32768, N=4096, K=1024.  Block tile 128x64xK32, 8 warps (4m x 2n),
// warp tile 32x32 = 2 m-tiles x 4 n-tiles of m16n8k8.
__global__ __launch_bounds__(256) void gemm_x_kernel(const float* __restrict__ X) {
    __shared__ float sA[128][36];
    __shared__ float sB[32][68];

    int tid  = threadIdx.x;
    int warp = tid >> 5, lane = tid & 31;
    int wm = warp >> 1, wn = warp & 1;
    int bm = blockIdx.y * 128, bn = blockIdx.x * 64;
    int grp = lane >> 2, tig = lane & 3;   // groupID, thread-in-group

    float acc[2][4][4];
    #pragma unroll
    for (int i = 0; i < 2; i++)
        #pragma unroll
        for (int j = 0; j < 4; j++)
            #pragma unroll
            for (int k = 0; k < 4; k++) acc[i][j][k] = 0.0f;

    int arow = tid >> 3;          // 0..31  (4 passes of 32 rows)
    int acol = (tid & 7) << 2;    // 0..28
    int brow = tid >> 4;          // 0..15  (2 passes of 16 rows)
    int bcol = (tid & 15) << 2;   // 0..60

    // prefetch k-tile 0
    float4 pA[4], pB[2];
    #pragma unroll
    for (int p = 0; p < 4; p++)
        pA[p] = *(const float4*)&X[(size_t)(bm + arow + p * 32) * D_SZ + acol];
    #pragma unroll
    for (int p = 0; p < 2; p++)
        pB[p] = *(const float4*)&g_Wx[(brow + p * 16) * G4 + bn + bcol];

    for (int kt = 0; kt < D_SZ; kt += 32) {
        #pragma unroll
        for (int p = 0; p < 4; p++) *(float4*)&sA[arow + p * 32][acol] = pA[p];
        #pragma unroll
        for (int p = 0; p < 2; p++) *(float4*)&sB[brow + p * 16][bcol] = pB[p];
        __syncthreads();

        int kn = (kt + 32 < D_SZ) ? kt + 32 : 0;   // wrap: wasted load, harmless
        #pragma unroll
        for (int p = 0; p < 4; p++)
            pA[p] = *(const float4*)&X[(size_t)(bm + arow + p * 32) * D_SZ + kn + acol];
        #pragma unroll
        for (int p = 0; p < 2; p++)
            pB[p] = *(const float4*)&g_Wx[(kn + brow + p * 16) * G4 + bn + bcol];

        #pragma unroll
        for (int k8 = 0; k8 < 4; k8++) {
            int kb = k8 * 8;
            uint32_t a[2][4], b[4][2];
            #pragma unroll
            for (int mt = 0; mt < 2; mt++) {
                int r = wm * 32 + mt * 16 + grp;
                a[mt][0] = f2tf32(sA[r    ][kb + tig]);
                a[mt][1] = f2tf32(sA[r + 8][kb + tig]);
                a[mt][2] = f2tf32(sA[r    ][kb + tig + 4]);
                a[mt][3] = f2tf32(sA[r + 8][kb + tig + 4]);
            }
            #pragma unroll
            for (int nt = 0; nt < 4; nt++) {
                int c = wn * 32 + nt * 8 + grp;
                b[nt][0] = f2tf32(sB[kb + tig    ][c]);
                b[nt][1] = f2tf32(sB[kb + tig + 4][c]);
            }
            #pragma unroll
            for (int mt = 0; mt < 2; mt++)
                #pragma unroll
                for (int nt = 0; nt < 4; nt++)
                    mma_tf32(acc[mt][nt], a[mt], b[nt]);
        }
        __syncthreads();
    }

    // epilogue: add bias, store fp32 Gx
    #pragma unroll
    for (int mt = 0; mt < 2; mt++) {
        #pragma unroll
        for (int nt = 0; nt < 4; nt++) {
            int col = bn + wn * 32 + nt * 8 + (tig << 1);
            float b0 = g_b4[col], b1 = g_b4[col + 1];
            int r0 = bm + wm * 32 + mt * 16 + grp;
            float2 v0 = make_float2(acc[mt][nt][0] + b0, acc[mt][nt][1] + b1);
            float2 v1 = make_float2(acc[mt][nt][2] + b0, acc[mt][nt][3] + b1);
            *(float2*)&g_Gx[(size_t)r0 * G4 + col] = v0;
            *(float2*)&g_Gx[(size_t)(r0 + 8) * G4 + col] = v1;
        }
    }
}

// ---------------- kernel 2: one LSTM step (GEMM + pointwise fused) ----------
// gates[64,4096] = h_prev @ Wh + Gx[t]; then f,i,g,o -> c,h.
// 128 blocks x 256 thr; block owns 32 packed gate-cols = 8 h-cols (all 4 gates),
// so its c-columns are exclusively owned. h double-buffered across steps.
__global__ __launch_bounds__(256) void lstm_step_kernel(float* __restrict__ out, int t,
                                                        int write_tails) {
    __shared__ float sH[64][36];
    __shared__ float sW[32][36];
    __shared__ float sG[64][33];

    int tid  = threadIdx.x;
    int warp = tid >> 5, lane = tid & 31;
    int wm = warp >> 1, wn = warp & 1;     // 4 m-warps x 2 n-warps
    int bn = blockIdx.x * 32;              // packed gate-col base
    int grp = lane >> 2, tig = lane & 3;

    const float* __restrict__ hbuf = g_h[t & 1];

    float acc[2][4];
    #pragma unroll
    for (int i = 0; i < 2; i++)
        #pragma unroll
        for (int j = 0; j < 4; j++) acc[i][j] = 0.0f;

    int hrow = tid >> 3;          // 0..31
    int hcol = (tid & 7) << 2;    // 0..28

    float4 pH0 = *(const float4*)&hbuf[hrow * H_SZ + hcol];
    float4 pH1 = *(const float4*)&hbuf[(hrow + 32) * H_SZ + hcol];
    float4 pW  = *(const float4*)&g_Wh[hrow * G4 + bn + hcol];

    for (int kt = 0; kt < H_SZ; kt += 32) {
        *(float4*)&sH[hrow][hcol]      = pH0;
        *(float4*)&sH[hrow + 32][hcol] = pH1;
        *(float4*)&sW[hrow][hcol]      = pW;
        __syncthreads();

        int kn = (kt + 32 < H_SZ) ? kt + 32 : 0;
        pH0 = *(const float4*)&hbuf[hrow * H_SZ + kn + hcol];
        pH1 = *(const float4*)&hbuf[(hrow + 32) * H_SZ + kn + hcol];
        pW  = *(const float4*)&g_Wh[(kn + hrow) * G4 + bn + hcol];

        #pragma unroll
        for (int k8 = 0; k8 < 4; k8++) {
            int kb = k8 * 8;
            uint32_t a[4], b[2][2];
            int r = wm * 16 + grp;
            a[0] = f2tf32(sH[r    ][kb + tig]);
            a[1] = f2tf32(sH[r + 8][kb + tig]);
            a[2] = f2tf32(sH[r    ][kb + tig + 4]);
            a[3] = f2tf32(sH[r + 8][kb + tig + 4]);
            #pragma unroll
            for (int nt = 0; nt < 2; nt++) {
                int c = wn * 16 + nt * 8 + grp;
                b[nt][0] = f2tf32(sW[kb + tig    ][c]);
                b[nt][1] = f2tf32(sW[kb + tig + 4][c]);
            }
            mma_tf32(acc[0], a, b[0]);
            mma_tf32(acc[1], a, b[1]);
        }
        __syncthreads();
    }

    // stash recurrent gate partial sums to smem for gate regrouping
    #pragma unroll
    for (int nt = 0; nt < 2; nt++) {
        int c = wn * 16 + nt * 8 + (tig << 1);
        int r = wm * 16 + grp;
        sG[r    ][c]     = acc[nt][0];
        sG[r    ][c + 1] = acc[nt][1];
        sG[r + 8][c]     = acc[nt][2];
        sG[r + 8][c + 1] = acc[nt][3];
    }
    __syncthreads();

    // pointwise: 512 (row, h-col) outputs per block, 2 per thread
    float* __restrict__ hout = g_h[(t + 1) & 1];
    #pragma unroll
    for (int p = 0; p < 2; p++) {
        int e = tid * 2 + p;          // 0..511
        int r = e >> 3;               // batch row 0..63
        int c = e & 7;                // local h-col 0..7
        float4 gx = *(const float4*)&g_Gx[(size_t)(t * B_SZ + r) * G4 + bn + c * 4];
        float pf = sG[r][c * 4 + 0] + gx.x;
        float pi = sG[r][c * 4 + 1] + gx.y;
        float pg = sG[r][c * 4 + 2] + gx.z;
        float po = sG[r][c * 4 + 3] + gx.w;
        float f = sigmoidf_fast(pf);
        float i = sigmoidf_fast(pi);
        float g = tanhf(pg);
        float o = sigmoidf_fast(po);
        int n  = (bn >> 2) + c;       // global h-col
        int ci = r * H_SZ + n;
        float cn = f * g_c[ci] + i * g;
        g_c[ci] = cn;
        float hn = o * tanhf(cn);
        hout[ci] = hn;
        out[(size_t)(t * B_SZ + r) * H_SZ + n] = hn;
        if (t == T_STEPS - 1 && write_tails) {
            out[(size_t)T_STEPS * B_SZ * H_SZ + ci] = hn;                      // hT
            out[(size_t)T_STEPS * B_SZ * H_SZ + B_SZ * H_SZ + ci] = cn;        // cT
        }
    }
}

// ---------------- launch ----------------
extern "C" void kernel_launch(void* const* d_in, const int* in_sizes, int n_in,
                              void* d_out, int out_size) {
    const float* x  = (const float*)d_in[0];
    const float* Wf = (const float*)d_in[1];
    const float* bf = (const float*)d_in[2];
    const float* Wi = (const float*)d_in[3];
    const float* bi = (const float*)d_in[4];
    const float* Wg = (const float*)d_in[5];
    const float* bg = (const float*)d_in[6];
    const float* Wo = (const float*)d_in[7];
    const float* bo = (const float*)d_in[8];
    float* out = (float*)d_out;

    int write_tails =
        (out_size >= T_STEPS * B_SZ * H_SZ + 2 * B_SZ * H_SZ) ? 1 : 0;

    pack_kernel<<<(D_SZ * G4 + 255) / 256, 256>>>(Wf, Wi, Wg, Wo, bf, bi, bg, bo);

    dim3 g1(G4 / 64, M_TOT / 128);
    gemm_x_kernel<<<g1, 256>>>(x);

    for (int t = 0; t < T_STEPS; t++)
        lstm_step_kernel<<<128, 256>>>(out, t, write_tails);
}

// round 2
// speedup vs baseline: 1.7979x; 1.7979x over previous
#include <cuda_runtime.h>
#include <cstdint>

#define T_STEPS 512
#define B_SZ 64
#define D_SZ 1024
#define H_SZ 1024
#define G4 4096
#define M_TOT (T_STEPS * B_SZ)   // 32768
#define NBLK 128                  // recurrence blocks (one wave, co-resident)

// ---------------- device scratch (static, allocation-free) ----------------
__device__ float    g_Wx[D_SZ * G4];                 // 16 MB packed col j = n*4+g
__device__ uint32_t g_Whp[NBLK * 32768];             // 16 MB tf32, MMA-fragment order
__device__ float    g_b4[G4];                        // packed bias
__device__ float    g_Gx[(size_t)M_TOT * G4];        // 512 MB x-projection (+bias)
__device__ float    g_h[2][B_SZ * H_SZ];             // double-buffered hidden state
__device__ unsigned g_bar;                           // monotonic grid barrier counter

// ---------------- helpers ----------------
__device__ __forceinline__ uint32_t f2tf32(float f) {
    uint32_t r;
    asm volatile("cvt.rna.tf32.f32 %0, %1;" : "=r"(r) : "f"(f));
    return r;
}

__device__ __forceinline__ void mma_tf32(float* c, const uint32_t* a, const uint32_t* b) {
    asm volatile(
        "mma.sync.aligned.m16n8k8.row.col.f32.tf32.tf32.f32 "
        "{%0,%1,%2,%3}, {%4,%5,%6,%7}, {%8,%9}, {%0,%1,%2,%3};"
        : "+f"(c[0]), "+f"(c[1]), "+f"(c[2]), "+f"(c[3])
        : "r"(a[0]), "r"(a[1]), "r"(a[2]), "r"(a[3]), "r"(b[0]), "r"(b[1]));
}

__device__ __forceinline__ float sigmoidf_fast(float x) {
    return 1.0f / (1.0f + __expf(-x));
}

// ---------------- kernel 0: repack weights/bias, zero state -----------------
// Packed gate layout: col j = n*4 + g (g: 0=f,1=i,2=g,3=o).
// g_Whp additionally holds the recurrent weights pre-shuffled into the exact
// per-(k8, wn, nt, lane, reg) MMA B-fragment order each recurrence block will
// copy verbatim into SMEM (tf32 bits).
__global__ void pack_kernel(const float* __restrict__ Wf, const float* __restrict__ Wi,
                            const float* __restrict__ Wg, const float* __restrict__ Wo,
                            const float* __restrict__ bf, const float* __restrict__ bi,
                            const float* __restrict__ bg, const float* __restrict__ bo) {
    int idx = blockIdx.x * blockDim.x + threadIdx.x;   // over 4M
    if (idx < D_SZ * G4) {
        // g_Wx: straight packed layout for the input GEMM
        {
            int k = idx >> 12;       // row
            int j = idx & 4095;      // packed col
            int n = j >> 2;
            int g = j & 3;
            const float* W = (g == 0) ? Wf : (g == 1) ? Wi : (g == 2) ? Wg : Wo;
            g_Wx[idx] = W[k * H_SZ + n];
        }
        // g_Whp: fragment-ordered tf32 recurrent weights
        {
            int blk  = idx >> 15;            // 0..127
            int off  = idx & 32767;
            int k8   = off >> 8;             // 0..127
            int rem  = off & 255;
            int wn   = rem >> 7;
            int nt   = (rem >> 6) & 1;
            int lane = (rem >> 1) & 31;
            int reg  = rem & 1;
            int grp = lane >> 2, tig = lane & 3;
            int k = k8 * 8 + tig + reg * 4;                // 0..1023
            int j = blk * 32 + wn * 16 + nt * 8 + grp;     // packed col
            int n = j >> 2, g = j & 3;
            const float* W = (g == 0) ? Wf : (g == 1) ? Wi : (g == 2) ? Wg : Wo;
            g_Whp[idx] = f2tf32(W[(D_SZ + k) * H_SZ + n]);
        }
    }
    if (idx < G4) {
        int n = idx >> 2, g = idx & 3;
        const float* bb = (g == 0) ? bf : (g == 1) ? bi : (g == 2) ? bg : bo;
        g_b4[idx] = bb[n];
    }
    if (idx < B_SZ * H_SZ) g_h[0][idx] = 0.0f;
    if (idx == 0) g_bar = 0u;
}

// ---------------- kernel 1: Gx = X @ Wx + b  (tf32 MMA) ----------------
// M=32768, N=4096, K=1024.  Block tile 128x128xK32, 8 warps (4m x 2n),
// warp tile 32x64 = 2 m-tiles x 8 n-tiles of m16n8k8.  tf32 conversion at STS.
__global__ __launch_bounds__(256) void gemm_x_kernel(const float* __restrict__ X) {
    __shared__ uint32_t sA[128][36];
    __shared__ uint32_t sB[32][132];

    int tid  = threadIdx.x;
    int warp = tid >> 5, lane = tid & 31;
    int wm = warp >> 1, wn = warp & 1;
    int bm = blockIdx.y * 128, bn = blockIdx.x * 128;
    int grp = lane >> 2, tig = lane & 3;

    float acc[2][8][4];
    #pragma unroll
    for (int i = 0; i < 2; i++)
        #pragma unroll
        for (int j = 0; j < 8; j++)
            #pragma unroll
            for (int k = 0; k < 4; k++) acc[i][j][k] = 0.0f;

    int arow = tid >> 3;          // 0..31 (4 passes of 32 rows)
    int acol = (tid & 7) << 2;    // 0..28
    int brow = tid >> 3;          // 0..31 (all 32 rows in one pass)
    int bcol = (tid & 7) << 2;    // 0..28, 4 col passes of 32

    float4 pA[4], pB[4];
    #pragma unroll
    for (int p = 0; p < 4; p++)
        pA[p] = *(const float4*)&X[(size_t)(bm + arow + p * 32) * D_SZ + acol];
    #pragma unroll
    for (int p = 0; p < 4; p++)
        pB[p] = *(const float4*)&g_Wx[brow * G4 + bn + bcol + p * 32];

    for (int kt = 0; kt < D_SZ; kt += 32) {
        #pragma unroll
        for (int p = 0; p < 4; p++) {
            uint32_t* d = &sA[arow + p * 32][acol];
            d[0] = f2tf32(pA[p].x); d[1] = f2tf32(pA[p].y);
            d[2] = f2tf32(pA[p].z); d[3] = f2tf32(pA[p].w);
        }
        #pragma unroll
        for (int p = 0; p < 4; p++) {
            uint32_t* d = &sB[brow][bcol + p * 32];
            d[0] = f2tf32(pB[p].x); d[1] = f2tf32(pB[p].y);
            d[2] = f2tf32(pB[p].z); d[3] = f2tf32(pB[p].w);
        }
        __syncthreads();

        int kn = (kt + 32 < D_SZ) ? kt + 32 : 0;   // wrap load, harmless
        #pragma unroll
        for (int p = 0; p < 4; p++)
            pA[p] = *(const float4*)&X[(size_t)(bm + arow + p * 32) * D_SZ + kn + acol];
        #pragma unroll
        for (int p = 0; p < 4; p++)
            pB[p] = *(const float4*)&g_Wx[(kn + brow) * G4 + bn + bcol + p * 32];

        #pragma unroll
        for (int k8 = 0; k8 < 4; k8++) {
            int kb = k8 * 8;
            uint32_t a[2][4], b[8][2];
            #pragma unroll
            for (int mt = 0; mt < 2; mt++) {
                int r = wm * 32 + mt * 16 + grp;
                a[mt][0] = sA[r    ][kb + tig];
                a[mt][1] = sA[r + 8][kb + tig];
                a[mt][2] = sA[r    ][kb + tig + 4];
                a[mt][3] = sA[r + 8][kb + tig + 4];
            }
            #pragma unroll
            for (int nt = 0; nt < 8; nt++) {
                int c = wn * 64 + nt * 8 + grp;
                b[nt][0] = sB[kb + tig    ][c];
                b[nt][1] = sB[kb + tig + 4][c];
            }
            #pragma unroll
            for (int mt = 0; mt < 2; mt++)
                #pragma unroll
                for (int nt = 0; nt < 8; nt++)
                    mma_tf32(acc[mt][nt], a[mt], b[nt]);
        }
        __syncthreads();
    }

    #pragma unroll
    for (int mt = 0; mt < 2; mt++) {
        #pragma unroll
        for (int nt = 0; nt < 8; nt++) {
            int col = bn + wn * 64 + nt * 8 + (tig << 1);
            float b0 = g_b4[col], b1 = g_b4[col + 1];
            int r0 = bm + wm * 32 + mt * 16 + grp;
            float2 v0 = make_float2(acc[mt][nt][0] + b0, acc[mt][nt][1] + b1);
            float2 v1 = make_float2(acc[mt][nt][2] + b0, acc[mt][nt][3] + b1);
            *(float2*)&g_Gx[(size_t)r0 * G4 + col] = v0;
            *(float2*)&g_Gx[(size_t)(r0 + 8) * G4 + col] = v1;
        }
    }
}

// ---------------- kernel 2: persistent recurrence ---------------------------
// 128 CTAs x 256 thr, all co-resident.  Each CTA owns 32 packed gate-cols
// (= 8 h-cols, all 4 gates) -> cell state lives in registers.  Wh slice is
// loaded into SMEM once (tf32, fragment order).  Per step: stream h via
// __ldcg (L2, never stale-L1), MMA, fused pointwise, global barrier.
__global__ __launch_bounds__(256, 1) void lstm_persistent_kernel(
        float* __restrict__ out, int write_tails) {
    extern __shared__ unsigned char smem[];
    uint32_t* sW = (uint32_t*)smem;                                    // 128 KB
    uint32_t (*sH)[68] = (uint32_t(*)[68])(smem + 131072);             // 17 KB
    float    (*sG)[33] = (float(*)[33])(smem + 131072 + 17408);        // 8.4 KB

    int tid  = threadIdx.x;
    int warp = tid >> 5, lane = tid & 31;
    int wm = warp >> 1, wn = warp & 1;
    int grp = lane >> 2, tig = lane & 3;
    int blk = blockIdx.x;

    // copy this block's Wh slice into SMEM once (already fragment-ordered)
    {
        const float4* src = (const float4*)(g_Whp + (size_t)blk * 32768);
        float4* dst = (float4*)sW;
        #pragma unroll
        for (int i = 0; i < 32; i++) dst[tid + i * 256] = src[tid + i * 256];
    }

    float creg[2] = {0.0f, 0.0f};
    __syncthreads();

    int hrow = tid >> 4;            // 0..15
    int hcol = (tid & 15) << 2;     // 0..60

    for (int t = 0; t < T_STEPS; t++) {
        const float* __restrict__ hbuf = g_h[t & 1];
        float* __restrict__ hout = g_h[(t + 1) & 1];

        // prefetch this thread's Gx quadruples (hidden behind the K loop)
        float4 gx[2];
        #pragma unroll
        for (int p = 0; p < 2; p++) {
            int e = tid * 2 + p, r = e >> 3, c = e & 7;
            gx[p] = __ldcg((const float4*)&g_Gx[(size_t)(t * B_SZ + r) * G4 +
                                                blk * 32 + c * 4]);
        }

        float acc0[4] = {0, 0, 0, 0}, acc1[4] = {0, 0, 0, 0};

        float4 pH[4];
        #pragma unroll
        for (int p = 0; p < 4; p++)
            pH[p] = __ldcg((const float4*)&hbuf[(hrow + p * 16) * H_SZ + hcol]);

        for (int kt = 0; kt < H_SZ; kt += 64) {
            #pragma unroll
            for (int p = 0; p < 4; p++) {
                uint32_t* d = &sH[hrow + p * 16][hcol];
                d[0] = f2tf32(pH[p].x); d[1] = f2tf32(pH[p].y);
                d[2] = f2tf32(pH[p].z); d[3] = f2tf32(pH[p].w);
            }
            __syncthreads();

            int kn = (kt + 64 < H_SZ) ? kt + 64 : 0;
            #pragma unroll
            for (int p = 0; p < 4; p++)
                pH[p] = __ldcg((const float4*)&hbuf[(hrow + p * 16) * H_SZ + kn + hcol]);

            int k8base = kt >> 3;
            #pragma unroll
            for (int k8l = 0; k8l < 8; k8l++) {
                int kb = k8l * 8;
                uint32_t a[4];
                int r0 = wm * 16 + grp;
                a[0] = sH[r0    ][kb + tig];
                a[1] = sH[r0 + 8][kb + tig];
                a[2] = sH[r0    ][kb + tig + 4];
                a[3] = sH[r0 + 8][kb + tig + 4];
                const uint32_t* bp = &sW[(((k8base + k8l) * 2 + wn) * 2) * 64 + lane * 2];
                uint2 b0 = *(const uint2*)bp;
                uint2 b1 = *(const uint2*)(bp + 64);
                mma_tf32(acc0, a, (const uint32_t*)&b0);
                mma_tf32(acc1, a, (const uint32_t*)&b1);
            }
            __syncthreads();
        }

        // stash recurrent partials for gate regrouping
        {
            int r = wm * 16 + grp;
            int c0 = wn * 16 + (tig << 1);
            sG[r    ][c0]     = acc0[0];
            sG[r    ][c0 + 1] = acc0[1];
            sG[r + 8][c0]     = acc0[2];
            sG[r + 8][c0 + 1] = acc0[3];
            int c1 = wn * 16 + 8 + (tig << 1);
            sG[r    ][c1]     = acc1[0];
            sG[r    ][c1 + 1] = acc1[1];
            sG[r + 8][c1]     = acc1[2];
            sG[r + 8][c1 + 1] = acc1[3];
        }
        __syncthreads();

        // fused pointwise: 2 (row, h-col) outputs per thread, c in registers
        #pragma unroll
        for (int p = 0; p < 2; p++) {
            int e = tid * 2 + p, r = e >> 3, c = e & 7;
            float pf = sG[r][c * 4 + 0] + gx[p].x;
            float pi = sG[r][c * 4 + 1] + gx[p].y;
            float pg = sG[r][c * 4 + 2] + gx[p].z;
            float po = sG[r][c * 4 + 3] + gx[p].w;
            float f = sigmoidf_fast(pf);
            float i = sigmoidf_fast(pi);
            float g = tanhf(pg);
            float o = sigmoidf_fast(po);
            float cn = f * creg[p] + i * g;
            creg[p] = cn;
            float hn = o * tanhf(cn);
            int n  = blk * 8 + c;
            int ci = r * H_SZ + n;
            hout[ci] = hn;
            out[(size_t)(t * B_SZ + r) * H_SZ + n] = hn;
            if (t == T_STEPS - 1 && write_tails) {
                out[(size_t)T_STEPS * B_SZ * H_SZ + ci] = hn;
                out[(size_t)T_STEPS * B_SZ * H_SZ + B_SZ * H_SZ + ci] = cn;
            }
        }

        // grid barrier (monotonic counter; reset each launch by pack_kernel)
        if (t < T_STEPS - 1) {
            __threadfence();
            __syncthreads();
            if (tid == 0) {
                atomicAdd(&g_bar, 1u);
                unsigned target = (unsigned)(t + 1) * (unsigned)gridDim.x;
                while (*((volatile unsigned*)&g_bar) < target) {
                    __nanosleep(32);
                }
            }
            __syncthreads();
        }
    }
}

// ---------------- launch ----------------
extern "C" void kernel_launch(void* const* d_in, const int* in_sizes, int n_in,
                              void* d_out, int out_size) {
    const float* x  = (const float*)d_in[0];
    const float* Wf = (const float*)d_in[1];
    const float* bf = (const float*)d_in[2];
    const float* Wi = (const float*)d_in[3];
    const float* bi = (const float*)d_in[4];
    const float* Wg = (const float*)d_in[5];
    const float* bg = (const float*)d_in[6];
    const float* Wo = (const float*)d_in[7];
    const float* bo = (const float*)d_in[8];
    float* out = (float*)d_out;

    int write_tails =
        (out_size >= T_STEPS * B_SZ * H_SZ + 2 * B_SZ * H_SZ) ? 1 : 0;

    static int smem_set = 0;
    if (!smem_set) {
        cudaFuncSetAttribute(lstm_persistent_kernel,
                             cudaFuncAttributeMaxDynamicSharedMemorySize, 156928);
        smem_set = 1;
    }

    pack_kernel<<<(D_SZ * G4 + 255) / 256, 256>>>(Wf, Wi, Wg, Wo, bf, bi, bg, bo);

    dim3 g1(G4 / 128, M_TOT / 128);
    gemm_x_kernel<<<g1, 256>>>(x);

    lstm_persistent_kernel<<<NBLK, 256, 156928>>>(out, write_tails);
}

// round 3
// speedup vs baseline: 3.3730x; 1.8760x over previous
#include <cuda_runtime.h>
#include <cuda_fp16.h>
#include <cstdint>

#define T_STEPS 512
#define B_SZ 64
#define D_SZ 1024
#define H_SZ 1024
#define G4 4096
#define M_TOT (T_STEPS * B_SZ)   // 32768
#define NBLK 128

// ---------------- device scratch (static, allocation-free) ----------------
__device__ __half   g_Xh[(size_t)M_TOT * D_SZ];    // 64 MB  x in fp16 [m][k]
__device__ __half   g_Wxh[D_SZ * G4];              // 8 MB   Wx fp16 [packed col][k]
__device__ __half   g_Whp[H_SZ * G4];              // 8 MB   Wh fp16 [packed col][k]
__device__ float    g_b4[G4];                      // packed bias
__device__ float    g_Gx[(size_t)M_TOT * G4];      // 512 MB x-projection (+bias)
__device__ __half   g_h[2][2 * 32768];             // h, dbl-buffered, split-k halves
__device__ unsigned g_bar;                         // monotonic grid barrier

// ---------------- helpers ----------------
__device__ __forceinline__ void mma_f16(float* c, const uint32_t* a, const uint32_t* b) {
    asm volatile(
        "mma.sync.aligned.m16n8k16.row.col.f32.f16.f16.f32 "
        "{%0,%1,%2,%3}, {%4,%5,%6,%7}, {%8,%9}, {%0,%1,%2,%3};"
        : "+f"(c[0]), "+f"(c[1]), "+f"(c[2]), "+f"(c[3])
        : "r"(a[0]), "r"(a[1]), "r"(a[2]), "r"(a[3]), "r"(b[0]), "r"(b[1]));
}

__device__ __forceinline__ void cp_async16(uint32_t smem_addr, const void* gptr) {
    asm volatile("cp.async.cg.shared.global [%0], [%1], 16;"
                 :: "r"(smem_addr), "l"(gptr));
}
#define CP_COMMIT() asm volatile("cp.async.commit_group;")
#define CP_WAIT(N)  asm volatile("cp.async.wait_group %0;" :: "n"(N))

__device__ __forceinline__ float sigmoid_fast(float x) {
    return __fdividef(1.0f, 1.0f + __expf(-x));
}
__device__ __forceinline__ float tanh_fast(float x) {
    float e = __expf(-2.0f * x);
    return __fdividef(1.0f - e, 1.0f + e);
}

// ---------------- kernel 0: repack weights/bias (fp16), init state ----------
// Packed gate layout: col j = n*4 + g (g: 0=f,1=i,2=g,3=o).
// Both weight packs stored transposed [col][k] so MMA B-fragment k-pairs are
// contiguous (one LDS.32 per fragment register).
__global__ void pack_kernel(const float* __restrict__ Wf, const float* __restrict__ Wi,
                            const float* __restrict__ Wg, const float* __restrict__ Wo,
                            const float* __restrict__ bf, const float* __restrict__ bi,
                            const float* __restrict__ bg, const float* __restrict__ bo) {
    int idx = blockIdx.x * blockDim.x + threadIdx.x;   // over 4M
    if (idx < D_SZ * G4) {
        int j = idx >> 10;       // packed col 0..4095
        int k = idx & 1023;
        int n = j >> 2;
        int g = j & 3;
        const float* W = (g == 0) ? Wf : (g == 1) ? Wi : (g == 2) ? Wg : Wo;
        g_Wxh[idx] = __float2half(W[k * H_SZ + n]);
        g_Whp[idx] = __float2half(W[(D_SZ + k) * H_SZ + n]);
    }
    if (idx < G4) {
        int n = idx >> 2, g = idx & 3;
        const float* bb = (g == 0) ? bf : (g == 1) ? bi : (g == 2) ? bg : bo;
        g_b4[idx] = bb[n];
    }
    if (idx < 2 * 32768) ((__half*)g_h)[idx] = __float2half(0.0f);   // h0 = 0
    if (idx == 0) g_bar = 0u;
}

// ---------------- kernel 0b: X -> fp16 ----------------
__global__ void convx_kernel(const float* __restrict__ X) {
    size_t i = (size_t)blockIdx.x * blockDim.x + threadIdx.x;   // x4 elements
    float4 v = ((const float4*)X)[i];
    __half2* dst = (__half2*)g_Xh;
    dst[2 * i]     = __floats2half2_rn(v.x, v.y);
    dst[2 * i + 1] = __floats2half2_rn(v.z, v.w);
}

// ---------------- kernel 1: Gx = X @ Wx + b (fp16 MMA, fp32 acc) ------------
// M=32768, N=4096, K=1024.  Block 128x128xK64, 8 warps (4m x 2n),
// warp 32x64 = 2m x 8n tiles of m16n8k16.
__global__ __launch_bounds__(256) void gemm_x_kernel() {
    __shared__ __half sA[128][72];
    __shared__ __half sB[128][72];

    int tid  = threadIdx.x;
    int warp = tid >> 5, lane = tid & 31;
    int wm = warp >> 1, wn = warp & 1;
    int bm = blockIdx.y * 128, bn = blockIdx.x * 128;
    int grp = lane >> 2, tig = lane & 3;

    float acc[2][8][4];
    #pragma unroll
    for (int i = 0; i < 2; i++)
        #pragma unroll
        for (int j = 0; j < 8; j++)
            #pragma unroll
            for (int k = 0; k < 4; k++) acc[i][j][k] = 0.0f;

    uint4 pA[4], pB[4];
    #pragma unroll
    for (int p = 0; p < 4; p++) {
        int l = tid + p * 256, r = l >> 3, w = l & 7;
        pA[p] = *(const uint4*)&g_Xh[(size_t)(bm + r) * D_SZ + w * 8];
        pB[p] = *(const uint4*)&g_Wxh[(size_t)(bn + r) * D_SZ + w * 8];
    }

    for (int kt = 0; kt < D_SZ; kt += 64) {
        #pragma unroll
        for (int p = 0; p < 4; p++) {
            int l = tid + p * 256, r = l >> 3, w = l & 7;
            *(uint4*)&sA[r][w * 8] = pA[p];
            *(uint4*)&sB[r][w * 8] = pB[p];
        }
        __syncthreads();

        int kn = (kt + 64 < D_SZ) ? kt + 64 : 0;   // wrap load, harmless
        #pragma unroll
        for (int p = 0; p < 4; p++) {
            int l = tid + p * 256, r = l >> 3, w = l & 7;
            pA[p] = *(const uint4*)&g_Xh[(size_t)(bm + r) * D_SZ + kn + w * 8];
            pB[p] = *(const uint4*)&g_Wxh[(size_t)(bn + r) * D_SZ + kn + w * 8];
        }

        #pragma unroll
        for (int k16 = 0; k16 < 4; k16++) {
            int ko = k16 * 16 + 2 * tig;
            uint32_t A[2][4], B[8][2];
            #pragma unroll
            for (int mt = 0; mt < 2; mt++) {
                int r = wm * 32 + mt * 16 + grp;
                A[mt][0] = *(const uint32_t*)&sA[r    ][ko];
                A[mt][1] = *(const uint32_t*)&sA[r + 8][ko];
                A[mt][2] = *(const uint32_t*)&sA[r    ][ko + 8];
                A[mt][3] = *(const uint32_t*)&sA[r + 8][ko + 8];
            }
            #pragma unroll
            for (int nt = 0; nt < 8; nt++) {
                int c = wn * 64 + nt * 8 + grp;
                B[nt][0] = *(const uint32_t*)&sB[c][ko];
                B[nt][1] = *(const uint32_t*)&sB[c][ko + 8];
            }
            #pragma unroll
            for (int mt = 0; mt < 2; mt++)
                #pragma unroll
                for (int nt = 0; nt < 8; nt++)
                    mma_f16(acc[mt][nt], A[mt], B[nt]);
        }
        __syncthreads();
    }

    #pragma unroll
    for (int mt = 0; mt < 2; mt++) {
        #pragma unroll
        for (int nt = 0; nt < 8; nt++) {
            int col = bn + wn * 64 + nt * 8 + (tig << 1);
            float b0 = g_b4[col], b1 = g_b4[col + 1];
            int r0 = bm + wm * 32 + mt * 16 + grp;
            float2 v0 = make_float2(acc[mt][nt][0] + b0, acc[mt][nt][1] + b1);
            float2 v1 = make_float2(acc[mt][nt][2] + b0, acc[mt][nt][3] + b1);
            *(float2*)&g_Gx[(size_t)r0 * G4 + col] = v0;
            *(float2*)&g_Gx[(size_t)(r0 + 8) * G4 + col] = v1;
        }
    }
}

// ---------------- kernel 2: persistent recurrence ---------------------------
// 128 CTAs x 256 thr.  CTA owns 32 packed gate-cols (8 h-cols).  Wh slice in
// SMEM fp16 (66 KB).  8 warps = 2m x 4k-split, warp tile 32 rows x 32 cols.
// h streamed per step via cp.async into double-buffered k-halves.
#define SW_STRIDE 1032   // halfs, conflict-free (2064 B % 128 = 16)
#define SH_STRIDE 520    // halfs, conflict-free (1040 B % 128 = 16)
#define OFF_H0 66048
#define OFF_H1 132608
#define OFF_G0 199168
#define OFF_G1 207616
#define SMEM_TOTAL_R 216064

__global__ __launch_bounds__(256, 1) void lstm_persistent_kernel(
        float* __restrict__ out, int write_tails) {
    extern __shared__ unsigned char smem[];
    __half* sW = (__half*)smem;
    __half* sH[2] = { (__half*)(smem + OFF_H0), (__half*)(smem + OFF_H1) };
    float (*sGA)[33] = (float(*)[33])(smem + OFF_G0);
    float (*sGB)[33] = (float(*)[33])(smem + OFF_G1);

    int tid  = threadIdx.x;
    int warp = tid >> 5, lane = tid & 31;
    int wk = warp >> 1, wm = warp & 1;     // 4 k-split x 2 m-split
    int grp = lane >> 2, tig = lane & 3;
    int blk = blockIdx.x;

    // one-time: Wh slice (already [col][k] fp16) -> padded SMEM
    {
        const uint4* src = (const uint4*)(g_Whp + (size_t)blk * 32768);
        #pragma unroll
        for (int i = 0; i < 16; i++) {
            int l = tid + i * 256;
            int c = l >> 7, w = l & 127;
            *(uint4*)(sW + c * SW_STRIDE + w * 8) = src[l];
        }
    }

    // per-thread cp.async smem destinations (same every step)
    uint32_t dstH[2];
    {
        int row = (tid) >> 6;  // recomputed per i below; base saved per buffer
        (void)row;
        dstH[0] = (uint32_t)__cvta_generic_to_shared(sH[0]);
        dstH[1] = (uint32_t)__cvta_generic_to_shared(sH[1]);
    }

    float creg[2] = {0.0f, 0.0f};
    __syncthreads();

    for (int t = 0; t < T_STEPS; t++) {
        const __half* __restrict__ hsrc = g_h[t & 1];

        // Gx prefetch (hidden behind the GEMM)
        float4 gx[2];
        #pragma unroll
        for (int p = 0; p < 2; p++) {
            int e = tid * 2 + p, r = e >> 3, c = e & 7;
            gx[p] = __ldcg((const float4*)&g_Gx[(size_t)(t * B_SZ + r) * G4 +
                                                blk * 32 + c * 4]);
        }

        // issue both k-halves of h via cp.async (L1-bypassing, no registers)
        #pragma unroll
        for (int h = 0; h < 2; h++) {
            const char* src = (const char*)(hsrc + h * 32768);
            #pragma unroll
            for (int i = 0; i < 16; i++) {
                int l = tid + i * 256;
                int row = l >> 6, w = l & 63;
                cp_async16(dstH[h] + (uint32_t)(row * SH_STRIDE + w * 8) * 2,
                           src + (size_t)l * 16);
            }
            CP_COMMIT();
        }

        float acc[2][4][4];
        #pragma unroll
        for (int i = 0; i < 2; i++)
            #pragma unroll
            for (int j = 0; j < 4; j++)
                #pragma unroll
                for (int k = 0; k < 4; k++) acc[i][j][k] = 0.0f;

        CP_WAIT(1);          // half 0 landed
        __syncthreads();

        #pragma unroll
        for (int h = 0; h < 2; h++) {
            const __half* hA = sH[h];
            #pragma unroll
            for (int kk = 0; kk < 8; kk++) {
                int k16l = wk * 8 + kk;
                int ko = k16l * 16 + 2 * tig;
                int kg = (h * 32 + k16l) * 16 + 2 * tig;
                uint32_t A0[4], A1[4];
                const __half* pa = hA + (wm * 32 + grp) * SH_STRIDE + ko;
                A0[0] = *(const uint32_t*)(pa);
                A0[1] = *(const uint32_t*)(pa + 8 * SH_STRIDE);
                A0[2] = *(const uint32_t*)(pa + 8);
                A0[3] = *(const uint32_t*)(pa + 8 * SH_STRIDE + 8);
                const __half* pa1 = pa + 16 * SH_STRIDE;
                A1[0] = *(const uint32_t*)(pa1);
                A1[1] = *(const uint32_t*)(pa1 + 8 * SH_STRIDE);
                A1[2] = *(const uint32_t*)(pa1 + 8);
                A1[3] = *(const uint32_t*)(pa1 + 8 * SH_STRIDE + 8);
                #pragma unroll
                for (int nt = 0; nt < 4; nt++) {
                    const __half* pb = sW + (nt * 8 + grp) * SW_STRIDE + kg;
                    uint32_t B[2] = { *(const uint32_t*)pb,
                                      *(const uint32_t*)(pb + 8) };
                    mma_f16(acc[0][nt], A0, B);
                    mma_f16(acc[1][nt], A1, B);
                }
            }
            if (h == 0) {
                CP_WAIT(0);  // half 1 landed
                __syncthreads();
            }
        }

        // 2-round k-split reduction into two SMEM buffers
        if ((wk & 1) == 0) {
            float (*d)[33] = (wk == 0) ? sGA : sGB;
            #pragma unroll
            for (int mt = 0; mt < 2; mt++)
                #pragma unroll
                for (int nt = 0; nt < 4; nt++) {
                    int r = wm * 32 + mt * 16 + grp, c = nt * 8 + 2 * tig;
                    d[r    ][c]     = acc[mt][nt][0];
                    d[r    ][c + 1] = acc[mt][nt][1];
                    d[r + 8][c]     = acc[mt][nt][2];
                    d[r + 8][c + 1] = acc[mt][nt][3];
                }
        }
        __syncthreads();
        if ((wk & 1) == 1) {
            float (*d)[33] = (wk == 1) ? sGA : sGB;
            #pragma unroll
            for (int mt = 0; mt < 2; mt++)
                #pragma unroll
                for (int nt = 0; nt < 4; nt++) {
                    int r = wm * 32 + mt * 16 + grp, c = nt * 8 + 2 * tig;
                    d[r    ][c]     += acc[mt][nt][0];
                    d[r    ][c + 1] += acc[mt][nt][1];
                    d[r + 8][c]     += acc[mt][nt][2];
                    d[r + 8][c + 1] += acc[mt][nt][3];
                }
        }
        __syncthreads();

        // fused pointwise: 2 (row, h-col) outputs per thread, c in registers
        __half* __restrict__ hout = g_h[(t + 1) & 1];
        #pragma unroll
        for (int p = 0; p < 2; p++) {
            int e = tid * 2 + p, r = e >> 3, c = e & 7;
            float pf = sGA[r][c * 4 + 0] + sGB[r][c * 4 + 0] + gx[p].x;
            float pi = sGA[r][c * 4 + 1] + sGB[r][c * 4 + 1] + gx[p].y;
            float pg = sGA[r][c * 4 + 2] + sGB[r][c * 4 + 2] + gx[p].z;
            float po = sGA[r][c * 4 + 3] + sGB[r][c * 4 + 3] + gx[p].w;
            float f = sigmoid_fast(pf);
            float i = sigmoid_fast(pi);
            float g = tanh_fast(pg);
            float o = sigmoid_fast(po);
            float cn = f * creg[p] + i * g;
            creg[p] = cn;
            float hn = o * tanh_fast(cn);
            int n = blk * 8 + c;
            hout[(n >> 9) * 32768 + r * 512 + (n & 511)] = __float2half(hn);
            out[(size_t)(t * B_SZ + r) * H_SZ + n] = hn;
            if (t == T_STEPS - 1 && write_tails) {
                int ci = r * H_SZ + n;
                out[(size_t)T_STEPS * B_SZ * H_SZ + ci] = hn;
                out[(size_t)T_STEPS * B_SZ * H_SZ + B_SZ * H_SZ + ci] = cn;
            }
        }

        // grid barrier (monotonic counter; reset each launch by pack_kernel)
        if (t < T_STEPS - 1) {
            __threadfence();
            __syncthreads();
            if (tid == 0) {
                atomicAdd(&g_bar, 1u);
                unsigned target = (unsigned)(t + 1) * (unsigned)gridDim.x;
                while (*((volatile unsigned*)&g_bar) < target) {
                    __nanosleep(20);
                }
            }
            __syncthreads();
        }
    }
}

// ---------------- launch ----------------
extern "C" void kernel_launch(void* const* d_in, const int* in_sizes, int n_in,
                              void* d_out, int out_size) {
    const float* x  = (const float*)d_in[0];
    const float* Wf = (const float*)d_in[1];
    const float* bf = (const float*)d_in[2];
    const float* Wi = (const float*)d_in[3];
    const float* bi = (const float*)d_in[4];
    const float* Wg = (const float*)d_in[5];
    const float* bg = (const float*)d_in[6];
    const float* Wo = (const float*)d_in[7];
    const float* bo = (const float*)d_in[8];
    float* out = (float*)d_out;

    int write_tails =
        (out_size >= T_STEPS * B_SZ * H_SZ + 2 * B_SZ * H_SZ) ? 1 : 0;

    static int smem_set = 0;
    if (!smem_set) {
        cudaFuncSetAttribute(lstm_persistent_kernel,
                             cudaFuncAttributeMaxDynamicSharedMemorySize,
                             SMEM_TOTAL_R);
        smem_set = 1;
    }

    pack_kernel<<<(D_SZ * G4 + 255) / 256, 256>>>(Wf, Wi, Wg, Wo, bf, bi, bg, bo);
    convx_kernel<<<(int)(((size_t)M_TOT * D_SZ / 4) / 256), 256>>>(x);

    dim3 g1(G4 / 128, M_TOT / 128);
    gemm_x_kernel<<<g1, 256>>>();

    lstm_persistent_kernel<<<NBLK, 256, SMEM_TOTAL_R>>>(out, write_tails);
}

// round 4
// speedup vs baseline: 3.6126x; 1.0711x over previous
#include <cuda_runtime.h>
#include <cuda_fp16.h>
#include <cstdint>

#define T_STEPS 512
#define B_SZ 64
#define D_SZ 1024
#define H_SZ 1024
#define G4 4096
#define M_TOT (T_STEPS * B_SZ)   // 32768
#define NBLK 128

// ---------------- device scratch (static, allocation-free) ----------------
__device__ __half   g_Xh[(size_t)M_TOT * D_SZ];    // 64 MB  x fp16 [m][k]
__device__ __half   g_Wxh[D_SZ * G4];              // 8 MB   Wx fp16 [packed col][k]
__device__ __half   g_Whp[H_SZ * G4];              // 8 MB   Wh fp16 [packed col][k]
__device__ float    g_b4[G4];                      // packed bias
__device__ __half   g_Gxh[(size_t)M_TOT * G4];     // 256 MB x-projection (+bias) fp16
__device__ __half   g_h[2][2 * 32768];             // h dbl-buffered, split-k halves
__device__ unsigned g_bar;                         // monotonic grid barrier

// ---------------- helpers ----------------
__device__ __forceinline__ void mma_f16(float* c, const uint32_t* a, const uint32_t* b) {
    asm volatile(
        "mma.sync.aligned.m16n8k16.row.col.f32.f16.f16.f32 "
        "{%0,%1,%2,%3}, {%4,%5,%6,%7}, {%8,%9}, {%0,%1,%2,%3};"
        : "+f"(c[0]), "+f"(c[1]), "+f"(c[2]), "+f"(c[3])
        : "r"(a[0]), "r"(a[1]), "r"(a[2]), "r"(a[3]), "r"(b[0]), "r"(b[1]));
}

__device__ __forceinline__ void ldsm_x4(uint32_t& r0, uint32_t& r1, uint32_t& r2,
                                        uint32_t& r3, uint32_t addr) {
    asm volatile("ldmatrix.sync.aligned.m8n8.x4.shared.b16 {%0,%1,%2,%3}, [%4];"
                 : "=r"(r0), "=r"(r1), "=r"(r2), "=r"(r3) : "r"(addr));
}

__device__ __forceinline__ void cp_async16(uint32_t smem_addr, const void* gptr) {
    asm volatile("cp.async.cg.shared.global [%0], [%1], 16;"
                 :: "r"(smem_addr), "l"(gptr));
}
#define CP_COMMIT() asm volatile("cp.async.commit_group;")
#define CP_WAIT(N)  asm volatile("cp.async.wait_group %0;" :: "n"(N))

__device__ __forceinline__ float sigmoid_fast(float x) {
    return __fdividef(1.0f, 1.0f + __expf(-x));
}
__device__ __forceinline__ float tanh_fast(float x) {
    float e = __expf(-2.0f * x);
    return __fdividef(1.0f - e, 1.0f + e);
}

// ---------------- kernel 0: repack weights/bias (fp16), init state ----------
// Packed gate layout: col j = n*4 + g (g: 0=f,1=i,2=g,3=o); weights stored
// transposed [col][k] (k-major) for row.col MMA.
__global__ void pack_kernel(const float* __restrict__ Wf, const float* __restrict__ Wi,
                            const float* __restrict__ Wg, const float* __restrict__ Wo,
                            const float* __restrict__ bf, const float* __restrict__ bi,
                            const float* __restrict__ bg, const float* __restrict__ bo) {
    int idx = blockIdx.x * blockDim.x + threadIdx.x;   // over 4M
    if (idx < D_SZ * G4) {
        int j = idx >> 10;       // packed col
        int k = idx & 1023;
        int n = j >> 2;
        int g = j & 3;
        const float* W = (g == 0) ? Wf : (g == 1) ? Wi : (g == 2) ? Wg : Wo;
        g_Wxh[idx] = __float2half(W[k * H_SZ + n]);
        g_Whp[idx] = __float2half(W[(D_SZ + k) * H_SZ + n]);
    }
    if (idx < G4) {
        int n = idx >> 2, g = idx & 3;
        const float* bb = (g == 0) ? bf : (g == 1) ? bi : (g == 2) ? bg : bo;
        g_b4[idx] = bb[n];
    }
    if (idx < 2 * 32768) ((__half*)g_h)[idx] = __float2half(0.0f);
    if (idx == 0) g_bar = 0u;
}

// ---------------- kernel 0b: X -> fp16 ----------------
__global__ void convx_kernel(const float* __restrict__ X) {
    size_t i = (size_t)blockIdx.x * blockDim.x + threadIdx.x;   // x4 elements
    float4 v = ((const float4*)X)[i];
    __half2* dst = (__half2*)g_Xh;
    dst[2 * i]     = __floats2half2_rn(v.x, v.y);
    dst[2 * i + 1] = __floats2half2_rn(v.z, v.w);
}

// ---------------- kernel 1: Gx = X @ Wx + b  (3-stage cp.async + ldmatrix) --
// M=32768 N=4096 K=1024.  Block 128x128xk64; 8 warps = 2m x 4n; warp 64x32 =
// 4mt x 4nt of m16n8k16.  Tiles SW128-swizzled, fragments via ldmatrix.x4.
#define GX_STAGE_B 32768          // bytes per stage (A 16K + B 16K)
#define GX_SMEM    (3 * GX_STAGE_B)

__global__ __launch_bounds__(256, 2) void gemm_x_kernel() {
    extern __shared__ unsigned char dsm[];
    uint32_t sbase = (uint32_t)__cvta_generic_to_shared(dsm);

    int tid  = threadIdx.x;
    int warp = tid >> 5, lane = tid & 31;
    int wm = warp >> 2, wn = warp & 3;
    int grp = lane >> 2, tig = lane & 3;
    int g8  = lane >> 3, lr = lane & 7;     // ldmatrix lane decomposition
    int bm = blockIdx.y * 128, bn = blockIdx.x * 128;

    // cp.async per-thread pattern: 4 chunks each for A and B per stage
    int cr[4], cc[4];
    uint32_t soff[4];
    #pragma unroll
    for (int i = 0; i < 4; i++) {
        int l = tid + i * 256;
        cr[i] = l >> 3;           // row 0..127
        cc[i] = l & 7;            // 16B chunk 0..7
        soff[i] = (uint32_t)(cr[i] * 128 + ((cc[i] ^ (cr[i] & 7)) * 16));
    }

    auto issue = [&](int stage, int kt) {
        uint32_t st = sbase + stage * GX_STAGE_B;
        #pragma unroll
        for (int i = 0; i < 4; i++) {
            cp_async16(st + soff[i],
                       &g_Xh[(size_t)(bm + cr[i]) * D_SZ + kt * 64 + cc[i] * 8]);
            cp_async16(st + 16384 + soff[i],
                       &g_Wxh[(size_t)(bn + cr[i]) * D_SZ + kt * 64 + cc[i] * 8]);
        }
        CP_COMMIT();
    };

    float acc[4][4][4];
    #pragma unroll
    for (int i = 0; i < 4; i++)
        #pragma unroll
        for (int j = 0; j < 4; j++)
            #pragma unroll
            for (int k = 0; k < 4; k++) acc[i][j][k] = 0.0f;

    issue(0, 0);
    issue(1, 1);

    for (int it = 0; it < 16; it++) {
        if (it < 15) { CP_WAIT(1); } else { CP_WAIT(0); }
        __syncthreads();
        if (it + 2 < 16) issue((it + 2) % 3, it + 2);

        uint32_t st = sbase + (it % 3) * GX_STAGE_B;
        #pragma unroll
        for (int k16 = 0; k16 < 4; k16++) {
            uint32_t A[4][4], Bf[2][4];
            #pragma unroll
            for (int mt = 0; mt < 4; mt++) {
                int m = wm * 64 + mt * 16 + (g8 & 1) * 8 + lr;
                int ch = k16 * 2 + (g8 >> 1);
                ldsm_x4(A[mt][0], A[mt][1], A[mt][2], A[mt][3],
                        st + m * 128 + ((ch ^ (m & 7)) * 16));
            }
            #pragma unroll
            for (int p = 0; p < 2; p++) {
                int n = wn * 32 + p * 16 + (g8 >> 1) * 8 + lr;
                int ch = k16 * 2 + (g8 & 1);
                ldsm_x4(Bf[p][0], Bf[p][1], Bf[p][2], Bf[p][3],
                        st + 16384 + n * 128 + ((ch ^ (n & 7)) * 16));
            }
            #pragma unroll
            for (int mt = 0; mt < 4; mt++)
                #pragma unroll
                for (int p = 0; p < 2; p++) {
                    mma_f16(acc[mt][2 * p],     A[mt], &Bf[p][0]);
                    mma_f16(acc[mt][2 * p + 1], A[mt], &Bf[p][2]);
                }
        }
        __syncthreads();
    }

    // epilogue: bias add, fp16 convert, stage through smem, coalesced store
    __half* sE = (__half*)dsm;     // 128 x 136 halfs (stride keeps uint4 align)
    #pragma unroll
    for (int mt = 0; mt < 4; mt++)
        #pragma unroll
        for (int nt = 0; nt < 4; nt++) {
            int lc = wn * 32 + nt * 8 + 2 * tig;
            int col = bn + lc;
            float b0 = g_b4[col], b1 = g_b4[col + 1];
            int r = wm * 64 + mt * 16 + grp;
            *(__half2*)&sE[r * 136 + lc] =
                __floats2half2_rn(acc[mt][nt][0] + b0, acc[mt][nt][1] + b1);
            *(__half2*)&sE[(r + 8) * 136 + lc] =
                __floats2half2_rn(acc[mt][nt][2] + b0, acc[mt][nt][3] + b1);
        }
    __syncthreads();
    #pragma unroll
    for (int i = 0; i < 8; i++) {
        int l = tid + i * 256;
        int row = l >> 4, c8 = l & 15;
        *(uint4*)&g_Gxh[(size_t)(bm + row) * G4 + bn + c8 * 8] =
            *(const uint4*)&sE[row * 136 + c8 * 8];
    }
}

// ---------------- kernel 2: persistent recurrence ---------------------------
#define SW_STRIDE 1032   // halfs
#define SH_STRIDE 520    // halfs
#define OFF_H0 66048
#define OFF_H1 132608
#define OFF_G0 199168
#define OFF_G1 207616
#define SMEM_TOTAL_R 216064

__global__ __launch_bounds__(256, 1) void lstm_persistent_kernel(
        float* __restrict__ out, int write_tails) {
    extern __shared__ unsigned char smem[];
    __half* sW = (__half*)smem;
    __half* sH[2] = { (__half*)(smem + OFF_H0), (__half*)(smem + OFF_H1) };
    float (*sGA)[33] = (float(*)[33])(smem + OFF_G0);
    float (*sGB)[33] = (float(*)[33])(smem + OFF_G1);

    int tid  = threadIdx.x;
    int warp = tid >> 5, lane = tid & 31;
    int wk = warp >> 1, wm = warp & 1;     // 4 k-split x 2 m-split
    int grp = lane >> 2, tig = lane & 3;
    int blk = blockIdx.x;

    // one-time: Wh slice ([col][k] fp16) -> padded SMEM
    {
        const uint4* src = (const uint4*)(g_Whp + (size_t)blk * 32768);
        #pragma unroll
        for (int i = 0; i < 16; i++) {
            int l = tid + i * 256;
            int c = l >> 7, w = l & 127;
            *(uint4*)(sW + c * SW_STRIDE + w * 8) = src[l];
        }
    }

    uint32_t dstH[2] = { (uint32_t)__cvta_generic_to_shared(sH[0]),
                         (uint32_t)__cvta_generic_to_shared(sH[1]) };

    float creg[2] = {0.0f, 0.0f};
    __syncthreads();

    for (int t = 0; t < T_STEPS; t++) {
        const __half* __restrict__ hsrc = g_h[t & 1];

        // Gx prefetch (fp16, hidden behind the GEMM)
        uint2 gxr[2];
        #pragma unroll
        for (int p = 0; p < 2; p++) {
            int e = tid * 2 + p, r = e >> 3, c = e & 7;
            gxr[p] = __ldcg((const uint2*)&g_Gxh[(size_t)(t * B_SZ + r) * G4 +
                                                 blk * 32 + c * 4]);
        }

        // stream h (both k-halves) via cp.async into double buffers
        #pragma unroll
        for (int h = 0; h < 2; h++) {
            const char* src = (const char*)(hsrc + h * 32768);
            #pragma unroll
            for (int i = 0; i < 16; i++) {
                int l = tid + i * 256;
                int row = l >> 6, w = l & 63;
                cp_async16(dstH[h] + (uint32_t)(row * SH_STRIDE + w * 8) * 2,
                           src + (size_t)l * 16);
            }
            CP_COMMIT();
        }

        float acc[2][4][4];
        #pragma unroll
        for (int i = 0; i < 2; i++)
            #pragma unroll
            for (int j = 0; j < 4; j++)
                #pragma unroll
                for (int k = 0; k < 4; k++) acc[i][j][k] = 0.0f;

        CP_WAIT(1);
        __syncthreads();

        #pragma unroll
        for (int h = 0; h < 2; h++) {
            const __half* hA = sH[h];
            #pragma unroll
            for (int kk = 0; kk < 8; kk++) {
                int k16l = wk * 8 + kk;
                int ko = k16l * 16 + 2 * tig;
                int kg = (h * 32 + k16l) * 16 + 2 * tig;
                uint32_t A0[4], A1[4];
                const __half* pa = hA + (wm * 32 + grp) * SH_STRIDE + ko;
                A0[0] = *(const uint32_t*)(pa);
                A0[1] = *(const uint32_t*)(pa + 8 * SH_STRIDE);
                A0[2] = *(const uint32_t*)(pa + 8);
                A0[3] = *(const uint32_t*)(pa + 8 * SH_STRIDE + 8);
                const __half* pa1 = pa + 16 * SH_STRIDE;
                A1[0] = *(const uint32_t*)(pa1);
                A1[1] = *(const uint32_t*)(pa1 + 8 * SH_STRIDE);
                A1[2] = *(const uint32_t*)(pa1 + 8);
                A1[3] = *(const uint32_t*)(pa1 + 8 * SH_STRIDE + 8);
                #pragma unroll
                for (int nt = 0; nt < 4; nt++) {
                    const __half* pb = sW + (nt * 8 + grp) * SW_STRIDE + kg;
                    uint32_t B[2] = { *(const uint32_t*)pb,
                                      *(const uint32_t*)(pb + 8) };
                    mma_f16(acc[0][nt], A0, B);
                    mma_f16(acc[1][nt], A1, B);
                }
            }
            if (h == 0) {
                CP_WAIT(0);
                __syncthreads();
            }
        }

        // 2-round k-split reduction
        if ((wk & 1) == 0) {
            float (*d)[33] = (wk == 0) ? sGA : sGB;
            #pragma unroll
            for (int mt = 0; mt < 2; mt++)
                #pragma unroll
                for (int nt = 0; nt < 4; nt++) {
                    int r = wm * 32 + mt * 16 + grp, c = nt * 8 + 2 * tig;
                    d[r    ][c]     = acc[mt][nt][0];
                    d[r    ][c + 1] = acc[mt][nt][1];
                    d[r + 8][c]     = acc[mt][nt][2];
                    d[r + 8][c + 1] = acc[mt][nt][3];
                }
        }
        __syncthreads();
        if ((wk & 1) == 1) {
            float (*d)[33] = (wk == 1) ? sGA : sGB;
            #pragma unroll
            for (int mt = 0; mt < 2; mt++)
                #pragma unroll
                for (int nt = 0; nt < 4; nt++) {
                    int r = wm * 32 + mt * 16 + grp, c = nt * 8 + 2 * tig;
                    d[r    ][c]     += acc[mt][nt][0];
                    d[r    ][c + 1] += acc[mt][nt][1];
                    d[r + 8][c]     += acc[mt][nt][2];
                    d[r + 8][c + 1] += acc[mt][nt][3];
                }
        }
        __syncthreads();

        // fused pointwise
        __half* __restrict__ hout = g_h[(t + 1) & 1];
        #pragma unroll
        for (int p = 0; p < 2; p++) {
            int e = tid * 2 + p, r = e >> 3, c = e & 7;
            float2 g01 = __half22float2(*(__half2*)&gxr[p].x);
            float2 g23 = __half22float2(*(__half2*)&gxr[p].y);
            float pf = sGA[r][c * 4 + 0] + sGB[r][c * 4 + 0] + g01.x;
            float pi = sGA[r][c * 4 + 1] + sGB[r][c * 4 + 1] + g01.y;
            float pg = sGA[r][c * 4 + 2] + sGB[r][c * 4 + 2] + g23.x;
            float po = sGA[r][c * 4 + 3] + sGB[r][c * 4 + 3] + g23.y;
            float f = sigmoid_fast(pf);
            float i = sigmoid_fast(pi);
            float g = tanh_fast(pg);
            float o = sigmoid_fast(po);
            float cn = f * creg[p] + i * g;
            creg[p] = cn;
            float hn = o * tanh_fast(cn);
            int n = blk * 8 + c;
            hout[(n >> 9) * 32768 + r * 512 + (n & 511)] = __float2half(hn);
            out[(size_t)(t * B_SZ + r) * H_SZ + n] = hn;
            if (t == T_STEPS - 1 && write_tails) {
                int ci = r * H_SZ + n;
                out[(size_t)T_STEPS * B_SZ * H_SZ + ci] = hn;
                out[(size_t)T_STEPS * B_SZ * H_SZ + B_SZ * H_SZ + ci] = cn;
            }
        }

        // grid barrier
        if (t < T_STEPS - 1) {
            __threadfence();
            __syncthreads();
            if (tid == 0) {
                atomicAdd(&g_bar, 1u);
                unsigned target = (unsigned)(t + 1) * (unsigned)gridDim.x;
                while (*((volatile unsigned*)&g_bar) < target) {
                    __nanosleep(20);
                }
            }
            __syncthreads();
        }
    }
}

// ---------------- launch ----------------
extern "C" void kernel_launch(void* const* d_in, const int* in_sizes, int n_in,
                              void* d_out, int out_size) {
    const float* x  = (const float*)d_in[0];
    const float* Wf = (const float*)d_in[1];
    const float* bf = (const float*)d_in[2];
    const float* Wi = (const float*)d_in[3];
    const float* bi = (const float*)d_in[4];
    const float* Wg = (const float*)d_in[5];
    const float* bg = (const float*)d_in[6];
    const float* Wo = (const float*)d_in[7];
    const float* bo = (const float*)d_in[8];
    float* out = (float*)d_out;

    int write_tails =
        (out_size >= T_STEPS * B_SZ * H_SZ + 2 * B_SZ * H_SZ) ? 1 : 0;

    static int smem_set = 0;
    if (!smem_set) {
        cudaFuncSetAttribute(lstm_persistent_kernel,
                             cudaFuncAttributeMaxDynamicSharedMemorySize,
                             SMEM_TOTAL_R);
        cudaFuncSetAttribute(gemm_x_kernel,
                             cudaFuncAttributeMaxDynamicSharedMemorySize,
                             GX_SMEM);
        smem_set = 1;
    }

    pack_kernel<<<(D_SZ * G4 + 255) / 256, 256>>>(Wf, Wi, Wg, Wo, bf, bi, bg, bo);
    convx_kernel<<<(int)(((size_t)M_TOT * D_SZ / 4) / 256), 256>>>(x);

    dim3 g1(G4 / 128, M_TOT / 128);
    gemm_x_kernel<<<g1, 256, GX_SMEM>>>();

    lstm_persistent_kernel<<<NBLK, 256, SMEM_TOTAL_R>>>(out, write_tails);
}